// round 1
// baseline (speedup 1.0000x reference)
#include <cuda_runtime.h>

// Problem constants (fixed by the dataset): B=2, C=6, H=W=512, radii {2,4}
#define HH 512
#define WW 512
#define HW (HH * WW)
#define CC 6
#define CCA_EPS 1e-6f

static __device__ __forceinline__ int refl(int p, int n) {
    // jnp.pad mode='reflect': -1 -> 1, n -> n-2
    return p < 0 ? -p : (p >= n ? 2 * n - 2 - p : p);
}

// Packed lower-triangular index (i >= j)
static __device__ __host__ __forceinline__ constexpr int P(int i, int j) {
    return i * (i + 1) / 2 + j;
}

#define XXi(i, j) (P(i, j))          // sum x_i x_j, j<=i   : 0..20
#define YYi(i, j) (21 + P(i, j))     // sum y_i y_j, j<=i   : 21..41
#define XYi(i, j) (42 + (i)*6 + (j)) // sum x_i y_j, all    : 42..77
#define XMi(a) (78 + (a))            // sum x_a             : 78..83
#define YMi(a) (84 + (a))            // sum y_a             : 84..89

// Accumulate (SGN=+1) or retire (SGN=-1) one padded row into the 90 window sums.
template <int R, int SGN>
static __device__ __forceinline__ void accum_row(const float* __restrict__ xb,
                                                 const float* __restrict__ yb,
                                                 int row, int xcol, float* A) {
    const int rbase = refl(row, HH) * WW;
#pragma unroll 1
    for (int dx = -R; dx <= R; ++dx) {
        const int c = refl(xcol + dx, WW);
        const int base = rbase + c;
        float xv[CC], yv[CC];
#pragma unroll
        for (int a = 0; a < CC; a++) {
            xv[a] = __ldg(xb + a * HW + base);
            yv[a] = __ldg(yb + a * HW + base);
        }
        float xs[CC], ys[CC];
#pragma unroll
        for (int a = 0; a < CC; a++) {
            xs[a] = (SGN > 0) ? xv[a] : -xv[a];
            ys[a] = (SGN > 0) ? yv[a] : -yv[a];
        }
#pragma unroll
        for (int i = 0; i < CC; i++) {
#pragma unroll
            for (int j = 0; j <= i; j++) {
                A[XXi(i, j)] = fmaf(xs[i], xv[j], A[XXi(i, j)]);
                A[YYi(i, j)] = fmaf(ys[i], yv[j], A[YYi(i, j)]);
            }
#pragma unroll
            for (int j = 0; j < CC; j++) {
                A[XYi(i, j)] = fmaf(xs[i], yv[j], A[XYi(i, j)]);
            }
            A[XMi(i)] += xs[i];
            A[YMi(i)] += ys[i];
        }
    }
}

// In-place: packed-lower SPD matrix -> packed-lower inv(chol(c)).
static __device__ __forceinline__ void chol_inv6(float* c) {
    float L[21];  // off-diagonals hold L[i][j]; diagonal slots hold 1/L[j][j]
#pragma unroll
    for (int j = 0; j < 6; j++) {
        float d = c[P(j, j)];
#pragma unroll
        for (int k = 0; k < j; k++) d = fmaf(-L[P(j, k)], L[P(j, k)], d);
        const float rs = rsqrtf(d);
        L[P(j, j)] = rs;
#pragma unroll
        for (int i = j + 1; i < 6; i++) {
            float s = c[P(i, j)];
#pragma unroll
            for (int k = 0; k < j; k++) s = fmaf(-L[P(i, k)], L[P(j, k)], s);
            L[P(i, j)] = s * rs;
        }
    }
    // Forward substitution: M = L^{-1}, written back into c (per-column, top-down)
#pragma unroll
    for (int j = 0; j < 6; j++) {
        c[P(j, j)] = L[P(j, j)];
#pragma unroll
        for (int i = j + 1; i < 6; i++) {
            float s = 0.f;
#pragma unroll
            for (int k = j; k < i; k++) s = fmaf(L[P(i, k)], c[P(k, j)], s);
            c[P(i, j)] = -L[P(i, i)] * s;
        }
    }
}

template <int R>
static __device__ __forceinline__ float cca_epilogue(const float* A) {
    constexpr float inv_n = 1.0f / float((2 * R + 1) * (2 * R + 1));
    float xm[6], ym[6];
#pragma unroll
    for (int a = 0; a < 6; a++) {
        xm[a] = A[XMi(a)] * inv_n;
        ym[a] = A[YMi(a)] * inv_n;
    }
    float cxx[21], cyy[21], cxy[36];
#pragma unroll
    for (int i = 0; i < 6; i++) {
#pragma unroll
        for (int j = 0; j <= i; j++) {
            cxx[P(i, j)] = fmaf(-xm[i], xm[j], A[XXi(i, j)] * inv_n);
            cyy[P(i, j)] = fmaf(-ym[i], ym[j], A[YYi(i, j)] * inv_n);
        }
        cxx[P(i, i)] += CCA_EPS;
        cyy[P(i, i)] += CCA_EPS;
#pragma unroll
        for (int j = 0; j < 6; j++) {
            cxy[i * 6 + j] = fmaf(-xm[i], ym[j], A[XYi(i, j)] * inv_n);
        }
    }
    chol_inv6(cxx);  // cxx now holds Mx = inv(Lx), packed lower
    chol_inv6(cyy);  // cyy now holds My = inv(Ly), packed lower

    // corr_ii = sum_{j<=i} sum_{k>=i} Mx[i,j] * Cxy[j,k] * My[k,i]
    float sim = 0.f;
#pragma unroll
    for (int i = 0; i < 6; i++) {
        float corr = 0.f;
#pragma unroll
        for (int k = i; k < 6; k++) {
            float t = 0.f;
#pragma unroll
            for (int j = 0; j <= i; j++) t = fmaf(cxx[P(i, j)], cxy[j * 6 + k], t);
            corr = fmaf(t, cyy[P(k, i)], corr);
        }
        sim += fabsf(corr);
    }
    return sim * (1.0f / 6.0f);
}

// Tiling: 32 columns per warp-row of threads, 4 warps per block,
// each thread slides a vertical window over RPW output rows of its column.
#define TW 32
#define WARPS 4
#define RPW 16
#define TILE_H (WARPS * RPW)

template <int R>
static __device__ void run_tile(const float* __restrict__ xb,
                                const float* __restrict__ yb,
                                float* __restrict__ ob,
                                int xcol, int y0, int ridx) {
    float A[90];
#pragma unroll
    for (int t = 0; t < 90; t++) A[t] = 0.f;
    // Prime the window with rows [y0-R, y0+R)
#pragma unroll 1
    for (int row = y0 - R; row < y0 + R; ++row) accum_row<R, 1>(xb, yb, row, xcol, A);
#pragma unroll 1
    for (int yy = y0; yy < y0 + RPW; ++yy) {
        accum_row<R, 1>(xb, yb, yy + R, xcol, A);  // window now [yy-R, yy+R]
        const float sim = cca_epilogue<R>(A);
        ob[((yy * WW + xcol) << 1) + ridx] = sim;
        accum_row<R, -1>(xb, yb, yy - R, xcol, A);
    }
}

__global__ void __launch_bounds__(TW * WARPS)
PatchCCAConv_kernel(const float* __restrict__ x, const float* __restrict__ y,
                    float* __restrict__ out) {
    const int b = blockIdx.z & 1;
    const int ridx = blockIdx.z >> 1;
    const int xcol = blockIdx.x * TW + threadIdx.x;
    const int y0 = blockIdx.y * TILE_H + threadIdx.y * RPW;
    const float* xb = x + b * CC * HW;
    const float* yb = y + b * CC * HW;
    float* ob = out + b * (HH * WW * 2);
    if (ridx == 0)
        run_tile<2>(xb, yb, ob, xcol, y0, 0);
    else
        run_tile<4>(xb, yb, ob, xcol, y0, 1);
}

extern "C" void kernel_launch(void* const* d_in, const int* in_sizes, int n_in,
                              void* d_out, int out_size) {
    const float* x = (const float*)d_in[0];
    const float* y = (const float*)d_in[1];
    float* out = (float*)d_out;
    (void)in_sizes; (void)n_in; (void)out_size;

    dim3 block(TW, WARPS, 1);
    dim3 grid(WW / TW, HH / TILE_H, 2 /*batch*/ * 2 /*radii*/);  // (16, 8, 4)
    PatchCCAConv_kernel<<<grid, block>>>(x, y, out);
}

// round 2
// speedup vs baseline: 1.0804x; 1.0804x over previous
#include <cuda_runtime.h>

// Problem constants (fixed by the dataset): B=2, C=6, H=W=512, radii {2,4}
#define HH 512
#define WW 512
#define HW (HH * WW)
#define CC 6
#define CCA_EPS 1e-6f

typedef unsigned long long u64;

// ---------- packed f32x2 helpers (sm_103a FFMA2 path) ----------
static __device__ __forceinline__ u64 pk2(float lo, float hi) {
    u64 r; asm("mov.b64 %0, {%1, %2};" : "=l"(r) : "f"(lo), "f"(hi)); return r;
}
static __device__ __forceinline__ u64 bc2(float v) {
    u64 r; asm("mov.b64 %0, {%1, %1};" : "=l"(r) : "f"(v)); return r;
}
static __device__ __forceinline__ void fma2(u64& d, u64 a, u64 b) {
    asm("fma.rn.f32x2 %0, %1, %2, %0;" : "+l"(d) : "l"(a), "l"(b));
}
static __device__ __forceinline__ void add2(u64& d, u64 a) {
    asm("add.rn.f32x2 %0, %0, %1;" : "+l"(d) : "l"(a));
}
static __device__ __forceinline__ void up2(u64 v, float& a, float& b) {
    asm("mov.b64 {%0, %1}, %2;" : "=f"(a), "=f"(b) : "l"(v));
}

static __device__ __forceinline__ int refl(int p, int n) {
    // jnp.pad mode='reflect': -1 -> 1, n -> n-2
    return p < 0 ? -p : (p >= n ? 2 * n - 2 - p : p);
}

// Packed lower-triangular index (i >= j)
static __device__ __host__ __forceinline__ constexpr int P(int i, int j) {
    return i * (i + 1) / 2 + j;
}

// Window-sum state, f32x2-packed along j.
struct Acc {
    u64 xx[9];   // XX triangle pairs: (1:01)(2:01)(3:01)(3:23)(4:01)(4:23)(5:01)(5:23)(5:45)
    u64 yy[9];
    u64 xy[18];  // full 6x6, row i pairs p=0..2
    u64 mx[3], my[3];
    float dxx[3];  // XX diag leftovers: (0,0) (2,2) (4,4)
    float dyy[3];
};

static __device__ __forceinline__ void acc_zero(Acc& A) {
#pragma unroll
    for (int t = 0; t < 9; t++) { A.xx[t] = 0ULL; A.yy[t] = 0ULL; }
#pragma unroll
    for (int t = 0; t < 18; t++) A.xy[t] = 0ULL;
#pragma unroll
    for (int t = 0; t < 3; t++) {
        A.mx[t] = 0ULL; A.my[t] = 0ULL; A.dxx[t] = 0.f; A.dyy[t] = 0.f;
    }
}

// Accumulate (SGN=+1) or retire (SGN=-1) one padded row into the window sums.
template <int R, int SGN>
static __device__ __forceinline__ void accum_row(const float* __restrict__ xb,
                                                 const float* __restrict__ yb,
                                                 int row, int xcol, Acc& A) {
    const int rbase = refl(row, HH) * WW;
#pragma unroll 1
    for (int dx = -R; dx <= R; ++dx) {
        const int base = rbase + refl(xcol + dx, WW);
        float xv[CC], yv[CC];
#pragma unroll
        for (int a = 0; a < CC; a++) {
            xv[a] = __ldg(xb + a * HW + base);
            yv[a] = __ldg(yb + a * HW + base);
        }
        // sign applied on the multiplier side only
        float mx[CC], my[CC];
#pragma unroll
        for (int a = 0; a < CC; a++) {
            mx[a] = (SGN > 0) ? xv[a] : -xv[a];
            my[a] = (SGN > 0) ? yv[a] : -yv[a];
        }
        u64 xp[3], yp[3];
#pragma unroll
        for (int p = 0; p < 3; p++) {
            xp[p] = pk2(xv[2 * p], xv[2 * p + 1]);
            yp[p] = pk2(yv[2 * p], yv[2 * p + 1]);
        }
        u64 bx[6], by[6];
#pragma unroll
        for (int a = 0; a < 6; a++) bx[a] = bc2(mx[a]);
#pragma unroll
        for (int a = 1; a < 6; a++) by[a] = bc2(my[a]);

        // XX triangle
        fma2(A.xx[0], bx[1], xp[0]);
        fma2(A.xx[1], bx[2], xp[0]);
        fma2(A.xx[2], bx[3], xp[0]); fma2(A.xx[3], bx[3], xp[1]);
        fma2(A.xx[4], bx[4], xp[0]); fma2(A.xx[5], bx[4], xp[1]);
        fma2(A.xx[6], bx[5], xp[0]); fma2(A.xx[7], bx[5], xp[1]); fma2(A.xx[8], bx[5], xp[2]);
        A.dxx[0] = fmaf(mx[0], xv[0], A.dxx[0]);
        A.dxx[1] = fmaf(mx[2], xv[2], A.dxx[1]);
        A.dxx[2] = fmaf(mx[4], xv[4], A.dxx[2]);
        // YY triangle
        fma2(A.yy[0], by[1], yp[0]);
        fma2(A.yy[1], by[2], yp[0]);
        fma2(A.yy[2], by[3], yp[0]); fma2(A.yy[3], by[3], yp[1]);
        fma2(A.yy[4], by[4], yp[0]); fma2(A.yy[5], by[4], yp[1]);
        fma2(A.yy[6], by[5], yp[0]); fma2(A.yy[7], by[5], yp[1]); fma2(A.yy[8], by[5], yp[2]);
        A.dyy[0] = fmaf(my[0], yv[0], A.dyy[0]);
        A.dyy[1] = fmaf(my[2], yv[2], A.dyy[1]);
        A.dyy[2] = fmaf(my[4], yv[4], A.dyy[2]);
        // XY full
#pragma unroll
        for (int i = 0; i < 6; i++) {
            fma2(A.xy[i * 3 + 0], bx[i], yp[0]);
            fma2(A.xy[i * 3 + 1], bx[i], yp[1]);
            fma2(A.xy[i * 3 + 2], bx[i], yp[2]);
        }
        // means
        if (SGN > 0) {
#pragma unroll
            for (int p = 0; p < 3; p++) { add2(A.mx[p], xp[p]); add2(A.my[p], yp[p]); }
        } else {
#pragma unroll
            for (int p = 0; p < 3; p++) {
                add2(A.mx[p], pk2(mx[2 * p], mx[2 * p + 1]));
                add2(A.my[p], pk2(my[2 * p], my[2 * p + 1]));
            }
        }
    }
}

// In-place: packed-lower SPD matrix -> packed-lower inv(chol(c)).
static __device__ __forceinline__ void chol_inv6(float* c) {
    float L[21];  // off-diagonals hold L[i][j]; diagonal slots hold 1/L[j][j]
#pragma unroll
    for (int j = 0; j < 6; j++) {
        float d = c[P(j, j)];
#pragma unroll
        for (int k = 0; k < j; k++) d = fmaf(-L[P(j, k)], L[P(j, k)], d);
        const float rs = rsqrtf(d);
        L[P(j, j)] = rs;
#pragma unroll
        for (int i = j + 1; i < 6; i++) {
            float s = c[P(i, j)];
#pragma unroll
            for (int k = 0; k < j; k++) s = fmaf(-L[P(i, k)], L[P(j, k)], s);
            L[P(i, j)] = s * rs;
        }
    }
    // Forward substitution: M = L^{-1}, written back into c
#pragma unroll
    for (int j = 0; j < 6; j++) {
        c[P(j, j)] = L[P(j, j)];
#pragma unroll
        for (int i = j + 1; i < 6; i++) {
            float s = 0.f;
#pragma unroll
            for (int k = j; k < i; k++) s = fmaf(L[P(i, k)], c[P(k, j)], s);
            c[P(i, j)] = -L[P(i, i)] * s;
        }
    }
}

template <int R>
static __device__ __forceinline__ float cca_epilogue(const Acc& A) {
    constexpr float inv_n = 1.0f / float((2 * R + 1) * (2 * R + 1));
    // unpack window sums
    float sxx[21], syy[21], sxy[36], sxm[6], sym[6];
    up2(A.xx[0], sxx[P(1, 0)], sxx[P(1, 1)]);
    up2(A.xx[1], sxx[P(2, 0)], sxx[P(2, 1)]);
    up2(A.xx[2], sxx[P(3, 0)], sxx[P(3, 1)]);
    up2(A.xx[3], sxx[P(3, 2)], sxx[P(3, 3)]);
    up2(A.xx[4], sxx[P(4, 0)], sxx[P(4, 1)]);
    up2(A.xx[5], sxx[P(4, 2)], sxx[P(4, 3)]);
    up2(A.xx[6], sxx[P(5, 0)], sxx[P(5, 1)]);
    up2(A.xx[7], sxx[P(5, 2)], sxx[P(5, 3)]);
    up2(A.xx[8], sxx[P(5, 4)], sxx[P(5, 5)]);
    sxx[P(0, 0)] = A.dxx[0]; sxx[P(2, 2)] = A.dxx[1]; sxx[P(4, 4)] = A.dxx[2];
    up2(A.yy[0], syy[P(1, 0)], syy[P(1, 1)]);
    up2(A.yy[1], syy[P(2, 0)], syy[P(2, 1)]);
    up2(A.yy[2], syy[P(3, 0)], syy[P(3, 1)]);
    up2(A.yy[3], syy[P(3, 2)], syy[P(3, 3)]);
    up2(A.yy[4], syy[P(4, 0)], syy[P(4, 1)]);
    up2(A.yy[5], syy[P(4, 2)], syy[P(4, 3)]);
    up2(A.yy[6], syy[P(5, 0)], syy[P(5, 1)]);
    up2(A.yy[7], syy[P(5, 2)], syy[P(5, 3)]);
    up2(A.yy[8], syy[P(5, 4)], syy[P(5, 5)]);
    syy[P(0, 0)] = A.dyy[0]; syy[P(2, 2)] = A.dyy[1]; syy[P(4, 4)] = A.dyy[2];
#pragma unroll
    for (int i = 0; i < 6; i++) {
#pragma unroll
        for (int p = 0; p < 3; p++) up2(A.xy[i * 3 + p], sxy[i * 6 + 2 * p], sxy[i * 6 + 2 * p + 1]);
    }
#pragma unroll
    for (int p = 0; p < 3; p++) {
        up2(A.mx[p], sxm[2 * p], sxm[2 * p + 1]);
        up2(A.my[p], sym[2 * p], sym[2 * p + 1]);
    }

    float xm[6], ym[6];
#pragma unroll
    for (int a = 0; a < 6; a++) { xm[a] = sxm[a] * inv_n; ym[a] = sym[a] * inv_n; }
    float cxx[21], cyy[21], cxy[36];
#pragma unroll
    for (int i = 0; i < 6; i++) {
#pragma unroll
        for (int j = 0; j <= i; j++) {
            cxx[P(i, j)] = fmaf(-xm[i], xm[j], sxx[P(i, j)] * inv_n);
            cyy[P(i, j)] = fmaf(-ym[i], ym[j], syy[P(i, j)] * inv_n);
        }
        cxx[P(i, i)] += CCA_EPS;
        cyy[P(i, i)] += CCA_EPS;
#pragma unroll
        for (int j = 0; j < 6; j++) {
            cxy[i * 6 + j] = fmaf(-xm[i], ym[j], sxy[i * 6 + j] * inv_n);
        }
    }
    chol_inv6(cxx);  // Mx = inv(Lx), packed lower
    chol_inv6(cyy);  // My = inv(Ly), packed lower

    // corr_ii = sum_{j<=i} sum_{k>=i} Mx[i,j] * Cxy[j,k] * My[k,i]
    float sim = 0.f;
#pragma unroll
    for (int i = 0; i < 6; i++) {
        float corr = 0.f;
#pragma unroll
        for (int k = i; k < 6; k++) {
            float t = 0.f;
#pragma unroll
            for (int j = 0; j <= i; j++) t = fmaf(cxx[P(i, j)], cxy[j * 6 + k], t);
            corr = fmaf(t, cyy[P(k, i)], corr);
        }
        sim += fabsf(corr);
    }
    return sim * (1.0f / 6.0f);
}

// Tiling: 32 columns per warp, 4 warps per block, each thread slides a
// vertical window over RPW output rows of its column.
#define TW 32
#define WARPS 4
#define RPW 16
#define TILE_H (WARPS * RPW)

template <int R>
static __device__ void run_tile(const float* __restrict__ xb,
                                const float* __restrict__ yb,
                                float* __restrict__ ob,
                                int xcol, int y0, int ridx) {
    Acc A;
    acc_zero(A);
    // Prime the window with rows [y0-R, y0+R)
#pragma unroll 1
    for (int row = y0 - R; row < y0 + R; ++row) accum_row<R, 1>(xb, yb, row, xcol, A);
#pragma unroll 1
    for (int yy = y0; yy < y0 + RPW; ++yy) {
        accum_row<R, 1>(xb, yb, yy + R, xcol, A);  // window now [yy-R, yy+R]
        const float sim = cca_epilogue<R>(A);
        ob[((yy * WW + xcol) << 1) + ridx] = sim;
        accum_row<R, -1>(xb, yb, yy - R, xcol, A);
    }
}

__global__ void __launch_bounds__(TW * WARPS)
PatchCCAConv_kernel(const float* __restrict__ x, const float* __restrict__ y,
                    float* __restrict__ out) {
    const int b = blockIdx.z & 1;
    const int ridx = blockIdx.z >> 1;
    const int xcol = blockIdx.x * TW + threadIdx.x;
    const int y0 = blockIdx.y * TILE_H + threadIdx.y * RPW;
    const float* xb = x + b * CC * HW;
    const float* yb = y + b * CC * HW;
    float* ob = out + b * (HH * WW * 2);
    if (ridx == 0)
        run_tile<2>(xb, yb, ob, xcol, y0, 0);
    else
        run_tile<4>(xb, yb, ob, xcol, y0, 1);
}

extern "C" void kernel_launch(void* const* d_in, const int* in_sizes, int n_in,
                              void* d_out, int out_size) {
    const float* x = (const float*)d_in[0];
    const float* y = (const float*)d_in[1];
    float* out = (float*)d_out;
    (void)in_sizes; (void)n_in; (void)out_size;

    dim3 block(TW, WARPS, 1);
    dim3 grid(WW / TW, HH / TILE_H, 2 /*batch*/ * 2 /*radii*/);  // (16, 8, 4)
    PatchCCAConv_kernel<<<grid, block>>>(x, y, out);
}

// round 7
// speedup vs baseline: 1.2501x; 1.1571x over previous
#include <cuda_runtime.h>

// Problem constants (fixed by the dataset): B=2, C=6, H=W=512, radii {2,4}
#define HH 512
#define WW 512
#define HW (HH * WW)
#define CC 6
#define CCA_EPS 1e-6f

typedef unsigned long long u64;

// ---------- packed f32x2 helpers (sm_103a FFMA2 path) ----------
static __device__ __forceinline__ u64 pk2(float lo, float hi) {
    u64 r; asm("mov.b64 %0, {%1, %2};" : "=l"(r) : "f"(lo), "f"(hi)); return r;
}
static __device__ __forceinline__ u64 bc2(float v) {
    u64 r; asm("mov.b64 %0, {%1, %1};" : "=l"(r) : "f"(v)); return r;
}
static __device__ __forceinline__ void fma2(u64& d, u64 a, u64 b) {
    asm("fma.rn.f32x2 %0, %1, %2, %0;" : "+l"(d) : "l"(a), "l"(b));
}
static __device__ __forceinline__ void add2(u64& d, u64 a) {
    asm("add.rn.f32x2 %0, %0, %1;" : "+l"(d) : "l"(a));
}
static __device__ __forceinline__ void sub2(u64& d, u64 a) {
    asm("sub.rn.f32x2 %0, %0, %1;" : "+l"(d) : "l"(a));
}
static __device__ __forceinline__ void up2(u64 v, float& a, float& b) {
    asm("mov.b64 {%0, %1}, %2;" : "=f"(a), "=f"(b) : "l"(v));
}

static __device__ __forceinline__ int refl(int p, int n) {
    // jnp.pad mode='reflect': -1 -> 1, n -> n-2
    return p < 0 ? -p : (p >= n ? 2 * n - 2 - p : p);
}

// Packed lower-triangular index (i >= j)
static __device__ __host__ __forceinline__ constexpr int P(int i, int j) {
    return i * (i + 1) / 2 + j;
}

// Window-sum state, f32x2-packed along j.
struct Acc {
    u64 xx[9];   // XX triangle pairs: (1:01)(2:01)(3:01)(3:23)(4:01)(4:23)(5:01)(5:23)(5:45)
    u64 yy[9];
    u64 xy[18];  // full 6x6, row i pairs p=0..2
    u64 mx[3], my[3];
    float dxx[3];  // XX diag leftovers: (0,0) (2,2) (4,4)
    float dyy[3];
};

static __device__ __forceinline__ void acc_zero(Acc& A) {
#pragma unroll
    for (int t = 0; t < 9; t++) { A.xx[t] = 0ULL; A.yy[t] = 0ULL; }
#pragma unroll
    for (int t = 0; t < 18; t++) A.xy[t] = 0ULL;
#pragma unroll
    for (int t = 0; t < 3; t++) {
        A.mx[t] = 0ULL; A.my[t] = 0ULL; A.dxx[t] = 0.f; A.dyy[t] = 0.f;
    }
}

// One sample's FMA work: SGN=+1 add, SGN=-1 retire.
template <int SGN>
static __device__ __forceinline__ void sample_fma(const float xv[CC], const float yv[CC], Acc& A) {
    float mxv[CC], myv[CC];
#pragma unroll
    for (int a = 0; a < CC; a++) {
        mxv[a] = (SGN > 0) ? xv[a] : -xv[a];
        myv[a] = (SGN > 0) ? yv[a] : -yv[a];
    }
    u64 xp[3], yp[3];
#pragma unroll
    for (int p = 0; p < 3; p++) {
        xp[p] = pk2(xv[2 * p], xv[2 * p + 1]);
        yp[p] = pk2(yv[2 * p], yv[2 * p + 1]);
    }
    u64 bx[6], by[6];
#pragma unroll
    for (int a = 0; a < 6; a++) bx[a] = bc2(mxv[a]);
#pragma unroll
    for (int a = 1; a < 6; a++) by[a] = bc2(myv[a]);

    // XX triangle
    fma2(A.xx[0], bx[1], xp[0]);
    fma2(A.xx[1], bx[2], xp[0]);
    fma2(A.xx[2], bx[3], xp[0]); fma2(A.xx[3], bx[3], xp[1]);
    fma2(A.xx[4], bx[4], xp[0]); fma2(A.xx[5], bx[4], xp[1]);
    fma2(A.xx[6], bx[5], xp[0]); fma2(A.xx[7], bx[5], xp[1]); fma2(A.xx[8], bx[5], xp[2]);
    A.dxx[0] = fmaf(mxv[0], xv[0], A.dxx[0]);
    A.dxx[1] = fmaf(mxv[2], xv[2], A.dxx[1]);
    A.dxx[2] = fmaf(mxv[4], xv[4], A.dxx[2]);
    // YY triangle
    fma2(A.yy[0], by[1], yp[0]);
    fma2(A.yy[1], by[2], yp[0]);
    fma2(A.yy[2], by[3], yp[0]); fma2(A.yy[3], by[3], yp[1]);
    fma2(A.yy[4], by[4], yp[0]); fma2(A.yy[5], by[4], yp[1]);
    fma2(A.yy[6], by[5], yp[0]); fma2(A.yy[7], by[5], yp[1]); fma2(A.yy[8], by[5], yp[2]);
    A.dyy[0] = fmaf(myv[0], yv[0], A.dyy[0]);
    A.dyy[1] = fmaf(myv[2], yv[2], A.dyy[1]);
    A.dyy[2] = fmaf(myv[4], yv[4], A.dyy[2]);
    // XY full
#pragma unroll
    for (int i = 0; i < 6; i++) {
        fma2(A.xy[i * 3 + 0], bx[i], yp[0]);
        fma2(A.xy[i * 3 + 1], bx[i], yp[1]);
        fma2(A.xy[i * 3 + 2], bx[i], yp[2]);
    }
    // means
    if (SGN > 0) {
#pragma unroll
        for (int p = 0; p < 3; p++) { add2(A.mx[p], xp[p]); add2(A.my[p], yp[p]); }
    } else {
#pragma unroll
        for (int p = 0; p < 3; p++) { sub2(A.mx[p], xp[p]); sub2(A.my[p], yp[p]); }
    }
}

// Priming: accumulate one padded row.
template <int R>
static __device__ __forceinline__ void accum_row(const float* __restrict__ xb,
                                                 const float* __restrict__ yb,
                                                 int row, int xcol, Acc& A) {
    const int rbase = refl(row, HH) * WW;
#pragma unroll 1
    for (int dx = -R; dx <= R; ++dx) {
        const int base = rbase + refl(xcol + dx, WW);
        float xv[CC], yv[CC];
#pragma unroll
        for (int a = 0; a < CC; a++) {
            xv[a] = __ldg(xb + a * HW + base);
            yv[a] = __ldg(yb + a * HW + base);
        }
        sample_fma<1>(xv, yv, A);
    }
}

// Fused slide: add row `rowAdd`, retire row `rowRet` (both padded row indices).
// Per dx iteration: 24 loads batched up front, then 2x independent FMA blocks.
template <int R>
static __device__ __forceinline__ void step_rows(const float* __restrict__ xb,
                                                 const float* __restrict__ yb,
                                                 int rowAdd, int rowRet, int xcol, Acc& A) {
    const int baseA = refl(rowAdd, HH) * WW;
    const int baseR = refl(rowRet, HH) * WW;
#pragma unroll (R == 2 ? 5 : 3)
    for (int dx = -R; dx <= R; ++dx) {
        const int c = refl(xcol + dx, WW);
        const int ia = baseA + c;
        const int ir = baseR + c;
        float xa[CC], ya[CC], xr[CC], yr[CC];
#pragma unroll
        for (int a = 0; a < CC; a++) {
            xa[a] = __ldg(xb + a * HW + ia);
            ya[a] = __ldg(yb + a * HW + ia);
            xr[a] = __ldg(xb + a * HW + ir);
            yr[a] = __ldg(yb + a * HW + ir);
        }
        sample_fma<1>(xa, ya, A);
        sample_fma<-1>(xr, yr, A);
    }
}

// In-place: packed-lower SPD matrix -> packed-lower inv(chol(c)).
static __device__ __forceinline__ void chol_inv6(float* c) {
    float L[21];  // off-diagonals hold L[i][j]; diagonal slots hold 1/L[j][j]
#pragma unroll
    for (int j = 0; j < 6; j++) {
        float d = c[P(j, j)];
#pragma unroll
        for (int k = 0; k < j; k++) d = fmaf(-L[P(j, k)], L[P(j, k)], d);
        const float rs = rsqrtf(d);
        L[P(j, j)] = rs;
#pragma unroll
        for (int i = j + 1; i < 6; i++) {
            float s = c[P(i, j)];
#pragma unroll
            for (int k = 0; k < j; k++) s = fmaf(-L[P(i, k)], L[P(j, k)], s);
            L[P(i, j)] = s * rs;
        }
    }
    // Forward substitution: M = L^{-1}, written back into c
#pragma unroll
    for (int j = 0; j < 6; j++) {
        c[P(j, j)] = L[P(j, j)];
#pragma unroll
        for (int i = j + 1; i < 6; i++) {
            float s = 0.f;
#pragma unroll
            for (int k = j; k < i; k++) s = fmaf(L[P(i, k)], c[P(k, j)], s);
            c[P(i, j)] = -L[P(i, i)] * s;
        }
    }
}

template <int R>
static __device__ __forceinline__ float cca_epilogue(const Acc& A) {
    constexpr float inv_n = 1.0f / float((2 * R + 1) * (2 * R + 1));
    // unpack window sums
    float sxx[21], syy[21], sxy[36], sxm[6], sym[6];
    up2(A.xx[0], sxx[P(1, 0)], sxx[P(1, 1)]);
    up2(A.xx[1], sxx[P(2, 0)], sxx[P(2, 1)]);
    up2(A.xx[2], sxx[P(3, 0)], sxx[P(3, 1)]);
    up2(A.xx[3], sxx[P(3, 2)], sxx[P(3, 3)]);
    up2(A.xx[4], sxx[P(4, 0)], sxx[P(4, 1)]);
    up2(A.xx[5], sxx[P(4, 2)], sxx[P(4, 3)]);
    up2(A.xx[6], sxx[P(5, 0)], sxx[P(5, 1)]);
    up2(A.xx[7], sxx[P(5, 2)], sxx[P(5, 3)]);
    up2(A.xx[8], sxx[P(5, 4)], sxx[P(5, 5)]);
    sxx[P(0, 0)] = A.dxx[0]; sxx[P(2, 2)] = A.dxx[1]; sxx[P(4, 4)] = A.dxx[2];
    up2(A.yy[0], syy[P(1, 0)], syy[P(1, 1)]);
    up2(A.yy[1], syy[P(2, 0)], syy[P(2, 1)]);
    up2(A.yy[2], syy[P(3, 0)], syy[P(3, 1)]);
    up2(A.yy[3], syy[P(3, 2)], syy[P(3, 3)]);
    up2(A.yy[4], syy[P(4, 0)], syy[P(4, 1)]);
    up2(A.yy[5], syy[P(4, 2)], syy[P(4, 3)]);
    up2(A.yy[6], syy[P(5, 0)], syy[P(5, 1)]);
    up2(A.yy[7], syy[P(5, 2)], syy[P(5, 3)]);
    up2(A.yy[8], syy[P(5, 4)], syy[P(5, 5)]);
    syy[P(0, 0)] = A.dyy[0]; syy[P(2, 2)] = A.dyy[1]; syy[P(4, 4)] = A.dyy[2];
#pragma unroll
    for (int i = 0; i < 6; i++) {
#pragma unroll
        for (int p = 0; p < 3; p++) up2(A.xy[i * 3 + p], sxy[i * 6 + 2 * p], sxy[i * 6 + 2 * p + 1]);
    }
#pragma unroll
    for (int p = 0; p < 3; p++) {
        up2(A.mx[p], sxm[2 * p], sxm[2 * p + 1]);
        up2(A.my[p], sym[2 * p], sym[2 * p + 1]);
    }

    float xm[6], ym[6];
#pragma unroll
    for (int a = 0; a < 6; a++) { xm[a] = sxm[a] * inv_n; ym[a] = sym[a] * inv_n; }
    float cxx[21], cyy[21], cxy[36];
#pragma unroll
    for (int i = 0; i < 6; i++) {
#pragma unroll
        for (int j = 0; j <= i; j++) {
            cxx[P(i, j)] = fmaf(-xm[i], xm[j], sxx[P(i, j)] * inv_n);
            cyy[P(i, j)] = fmaf(-ym[i], ym[j], syy[P(i, j)] * inv_n);
        }
        cxx[P(i, i)] += CCA_EPS;
        cyy[P(i, i)] += CCA_EPS;
#pragma unroll
        for (int j = 0; j < 6; j++) {
            cxy[i * 6 + j] = fmaf(-xm[i], ym[j], sxy[i * 6 + j] * inv_n);
        }
    }
    chol_inv6(cxx);  // Mx = inv(Lx), packed lower
    chol_inv6(cyy);  // My = inv(Ly), packed lower

    // corr_ii = sum_{j<=i} sum_{k>=i} Mx[i,j] * Cxy[j,k] * My[k,i]
    float sim = 0.f;
#pragma unroll
    for (int i = 0; i < 6; i++) {
        float corr = 0.f;
#pragma unroll
        for (int k = i; k < 6; k++) {
            float t = 0.f;
#pragma unroll
            for (int j = 0; j <= i; j++) t = fmaf(cxx[P(i, j)], cxy[j * 6 + k], t);
            corr = fmaf(t, cyy[P(k, i)], corr);
        }
        sim += fabsf(corr);
    }
    return sim * (1.0f / 6.0f);
}

// Tiling: 32 columns per warp, 4 warps per block, each thread slides a
// vertical window over RPW output rows of its column.
#define TW 32
#define WARPS 4
#define RPW 16
#define TILE_H (WARPS * RPW)

template <int R>
static __device__ void run_tile(const float* __restrict__ xb,
                                const float* __restrict__ yb,
                                float* __restrict__ ob,
                                int xcol, int y0, int ridx) {
    Acc A;
    acc_zero(A);
    // Prime the window with rows [y0-R-1, y0+R-1] (2R+1 rows; row y0-R-1 is
    // the stale row retired by the first fused step).
#pragma unroll 1
    for (int row = y0 - R - 1; row <= y0 + R - 1; ++row) accum_row<R>(xb, yb, row, xcol, A);
#pragma unroll 1
    for (int yy = y0; yy < y0 + RPW; ++yy) {
        step_rows<R>(xb, yb, yy + R, yy - R - 1, xcol, A);  // window -> [yy-R, yy+R]
        const float sim = cca_epilogue<R>(A);
        ob[((yy * WW + xcol) << 1) + ridx] = sim;
    }
}

__global__ void __launch_bounds__(TW * WARPS, 3)
PatchCCAConv_kernel(const float* __restrict__ x, const float* __restrict__ y,
                    float* __restrict__ out) {
    // z = 0,1 -> r=4 (long blocks scheduled first); z = 2,3 -> r=2
    const int b = blockIdx.z & 1;
    const bool is_r4 = blockIdx.z < 2;
    const int xcol = blockIdx.x * TW + threadIdx.x;
    const int y0 = blockIdx.y * TILE_H + threadIdx.y * RPW;
    const float* xb = x + b * CC * HW;
    const float* yb = y + b * CC * HW;
    float* ob = out + b * (HH * WW * 2);
    if (is_r4)
        run_tile<4>(xb, yb, ob, xcol, y0, 1);
    else
        run_tile<2>(xb, yb, ob, xcol, y0, 0);
}

extern "C" void kernel_launch(void* const* d_in, const int* in_sizes, int n_in,
                              void* d_out, int out_size) {
    const float* x = (const float*)d_in[0];
    const float* y = (const float*)d_in[1];
    float* out = (float*)d_out;
    (void)in_sizes; (void)n_in; (void)out_size;

    dim3 block(TW, WARPS, 1);
    dim3 grid(WW / TW, HH / TILE_H, 4);  // (16, 8, 4): z<2 r=4, z>=2 r=2
    PatchCCAConv_kernel<<<grid, block>>>(x, y, out);
}